// round 10
// baseline (speedup 1.0000x reference)
#include <cuda_runtime.h>
#include <cuda_bf16.h>
#include <cstdint>

// Problem constants
#define Bc 2
#define Tc 2048
#define Cc 1024
#define Hc 16
#define Dc 64
#define Mtot 4096
#define BHc 32

// ---------------------------------------------------------------------------
// Scratch (__device__ globals)
// ---------------------------------------------------------------------------
__device__ __align__(256) __nv_bfloat16 g_xh[Mtot * Cc];
__device__ __align__(256) __nv_bfloat16 g_xl[Mtot * Cc];
__device__ __align__(256) __nv_bfloat16 g_qh[BHc * Tc * Dc];
__device__ __align__(256) __nv_bfloat16 g_ql[BHc * Tc * Dc];
__device__ __align__(256) __nv_bfloat16 g_kh[BHc * Tc * Dc];
__device__ __align__(256) __nv_bfloat16 g_kl[BHc * Tc * Dc];
__device__ __align__(256) __nv_bfloat16 g_vh[BHc * Tc * Dc];
__device__ __align__(256) __nv_bfloat16 g_vl[BHc * Tc * Dc];
__device__ __align__(256) __nv_bfloat16 g_yh[Mtot * Cc];
__device__ __align__(256) __nv_bfloat16 g_yl[Mtot * Cc];
__device__ __align__(256) __nv_bfloat16 g_wqh[Cc * Cc];
__device__ __align__(256) __nv_bfloat16 g_wql[Cc * Cc];
__device__ __align__(256) __nv_bfloat16 g_wkh[Cc * Cc];
__device__ __align__(256) __nv_bfloat16 g_wkl[Cc * Cc];
__device__ __align__(256) __nv_bfloat16 g_wvh[Cc * Cc];
__device__ __align__(256) __nv_bfloat16 g_wvl[Cc * Cc];
__device__ __align__(256) __nv_bfloat16 g_wph[Cc * Cc];
__device__ __align__(256) __nv_bfloat16 g_wpl[Cc * Cc];

// ---------------------------------------------------------------------------
// Baseline-PTX helpers (sm_103-safe: no 'a'-suffix features)
// ---------------------------------------------------------------------------
__device__ __forceinline__ uint32_t cvta_s(const void* p) {
    return (uint32_t)__cvta_generic_to_shared(p);
}
__device__ __forceinline__ void ldsm4(uint32_t a, uint32_t& r0, uint32_t& r1,
                                      uint32_t& r2, uint32_t& r3) {
    asm volatile("ldmatrix.sync.aligned.m8n8.x4.shared.b16 {%0,%1,%2,%3}, [%4];"
                 : "=r"(r0), "=r"(r1), "=r"(r2), "=r"(r3) : "r"(a));
}
__device__ __forceinline__ void ldsm2t(uint32_t a, uint32_t& r0, uint32_t& r1) {
    asm volatile("ldmatrix.sync.aligned.m8n8.x2.trans.shared.b16 {%0,%1}, [%2];"
                 : "=r"(r0), "=r"(r1) : "r"(a));
}
__device__ __forceinline__ void mma16816(float* d, const uint32_t* a,
                                         const uint32_t* b) {
    asm volatile(
        "mma.sync.aligned.m16n8k16.row.col.f32.bf16.bf16.f32 "
        "{%0,%1,%2,%3}, {%4,%5,%6,%7}, {%8,%9}, {%0,%1,%2,%3};"
        : "+f"(d[0]), "+f"(d[1]), "+f"(d[2]), "+f"(d[3])
        : "r"(a[0]), "r"(a[1]), "r"(a[2]), "r"(a[3]), "r"(b[0]), "r"(b[1]));
}
#define CPA16(s, g) \
    asm volatile("cp.async.cg.shared.global [%0], [%1], 16;" :: "r"(s), "l"(g))
#define CPCOMMIT() asm volatile("cp.async.commit_group;" ::: "memory")
#define CPWAIT(n)  asm volatile("cp.async.wait_group %0;" :: "n"(n) : "memory")

__device__ __forceinline__ uint32_t pack_bf(__nv_bfloat16 a, __nv_bfloat16 b) {
    __nv_bfloat162 t = __halves2bfloat162(a, b);
    return *reinterpret_cast<uint32_t*>(&t);
}
__device__ __forceinline__ void split_pack(float e, float o, uint32_t& hi,
                                           uint32_t& lo) {
    __nv_bfloat16 he = __float2bfloat16_rn(e);
    __nv_bfloat16 ho = __float2bfloat16_rn(o);
    __nv_bfloat16 le = __float2bfloat16_rn(e - __bfloat162float(he));
    __nv_bfloat16 lo_ = __float2bfloat16_rn(o - __bfloat162float(ho));
    hi = pack_bf(he, ho);
    lo = pack_bf(le, lo_);
}

// ---------------------------------------------------------------------------
// fp32 -> (hi, lo) bf16 split
// ---------------------------------------------------------------------------
__global__ __launch_bounds__(256) void split_bf16(const float* __restrict__ src,
                                                  __nv_bfloat16* __restrict__ hi,
                                                  __nv_bfloat16* __restrict__ lo) {
    int i = blockIdx.x * blockDim.x + threadIdx.x;
    float4 v = ((const float4*)src)[i];
    __nv_bfloat16 h0 = __float2bfloat16_rn(v.x);
    __nv_bfloat16 h1 = __float2bfloat16_rn(v.y);
    __nv_bfloat16 h2 = __float2bfloat16_rn(v.z);
    __nv_bfloat16 h3 = __float2bfloat16_rn(v.w);
    __nv_bfloat16 l0 = __float2bfloat16_rn(v.x - __bfloat162float(h0));
    __nv_bfloat16 l1 = __float2bfloat16_rn(v.y - __bfloat162float(h1));
    __nv_bfloat16 l2 = __float2bfloat16_rn(v.z - __bfloat162float(h2));
    __nv_bfloat16 l3 = __float2bfloat16_rn(v.w - __bfloat162float(h3));
    ((__nv_bfloat162*)hi)[2 * i]     = __halves2bfloat162(h0, h1);
    ((__nv_bfloat162*)hi)[2 * i + 1] = __halves2bfloat162(h2, h3);
    ((__nv_bfloat162*)lo)[2 * i]     = __halves2bfloat162(l0, l1);
    ((__nv_bfloat162*)lo)[2 * i + 1] = __halves2bfloat162(l2, l3);
}

// ---------------------------------------------------------------------------
// GEMM via mma.sync: out = (Ah+Al) @ (Bh+Bl)^T + bias
// CTA 128x128, 8 warps (warp tile 32x64), BK=32, 3-stage cp.async ring,
// ONE __syncthreads per K-tile.
// ---------------------------------------------------------------------------
#define SRB 80u
#define MATB (128u * SRB)
#define STAGEB (4u * MATB)          // 40960 B
#define GEMM_SMEM (3u * STAGEB)     // 122880 B
#define GNT (Cc / 32)               // 32 K-tiles

__device__ __forceinline__ void gemm_load_stage(
    uint32_t base, int tid, int m0, int n0, int k0,
    const __nv_bfloat16* __restrict__ Ah, const __nv_bfloat16* __restrict__ Al,
    const __nv_bfloat16* __restrict__ Bh, const __nv_bfloat16* __restrict__ Bl) {
#pragma unroll
    for (int it = 0; it < 2; it++) {
        int idx = tid + it * 256;
        int row = idx >> 2, seg = idx & 3;
        uint32_t so = (uint32_t)row * SRB + (uint32_t)seg * 16u;
        size_t ga = (size_t)(m0 + row) * Cc + k0 + seg * 8;
        size_t gb = (size_t)(n0 + row) * Cc + k0 + seg * 8;
        CPA16(base + so, Ah + ga);
        CPA16(base + MATB + so, Al + ga);
        CPA16(base + 2u * MATB + so, Bh + gb);
        CPA16(base + 3u * MATB + so, Bl + gb);
    }
}

template <int MODE>
__global__ __launch_bounds__(256) void gemm_mma(
    const __nv_bfloat16* __restrict__ Ah, const __nv_bfloat16* __restrict__ Al,
    const __nv_bfloat16* __restrict__ Bh, const __nv_bfloat16* __restrict__ Bl,
    const float* __restrict__ bias,
    void* __restrict__ outH, __nv_bfloat16* __restrict__ outL) {
    extern __shared__ __align__(16) char smg[];
    const uint32_t sb = cvta_s(smg);
    const int tid = threadIdx.x, lane = tid & 31, wid = tid >> 5;
    const int wm = wid & 3, wn = wid >> 2;
    const int m0 = blockIdx.y * 128, n0 = blockIdx.x * 128;

    float acc[2][8][4];
#pragma unroll
    for (int i = 0; i < 2; i++)
#pragma unroll
        for (int j = 0; j < 8; j++)
#pragma unroll
            for (int k = 0; k < 4; k++) acc[i][j][k] = 0.0f;

    gemm_load_stage(sb, tid, m0, n0, 0, Ah, Al, Bh, Bl);
    CPCOMMIT();
    gemm_load_stage(sb + STAGEB, tid, m0, n0, 32, Ah, Al, Bh, Bl);
    CPCOMMIT();

    const int arow = wm * 32 + (lane & 15);
    const int akof = (lane >> 4) << 3;
    const int brow = (lane & 7) + ((lane & 16) >> 1);
    const int bkof = lane & 8;

    for (int kt = 0; kt < GNT; kt++) {
        if (kt + 1 < GNT) { CPWAIT(1); } else { CPWAIT(0); }
        __syncthreads();
        if (kt + 2 < GNT) {
            gemm_load_stage(sb + (uint32_t)((kt + 2) % 3) * STAGEB, tid, m0, n0,
                            (kt + 2) * 32, Ah, Al, Bh, Bl);
            CPCOMMIT();
        }
        const uint32_t base = sb + (uint32_t)(kt % 3) * STAGEB;
#pragma unroll
        for (int ks = 0; ks < 2; ks++) {
            uint32_t ah[2][4], al[2][4];
            const uint32_t acb = (uint32_t)(ks * 16 + akof) * 2u;
#pragma unroll
            for (int mf = 0; mf < 2; mf++) {
                uint32_t ao = (uint32_t)(arow + mf * 16) * SRB + acb;
                ldsm4(base + ao, ah[mf][0], ah[mf][1], ah[mf][2], ah[mf][3]);
                ldsm4(base + MATB + ao, al[mf][0], al[mf][1], al[mf][2], al[mf][3]);
            }
            uint32_t bh[4][4], bl[4][4];
            const uint32_t bcb = (uint32_t)(ks * 16 + bkof) * 2u;
#pragma unroll
            for (int ng = 0; ng < 4; ng++) {
                uint32_t bo = (uint32_t)(wn * 64 + ng * 16 + brow) * SRB + bcb;
                ldsm4(base + 2u * MATB + bo, bh[ng][0], bh[ng][1], bh[ng][2], bh[ng][3]);
                ldsm4(base + 3u * MATB + bo, bl[ng][0], bl[ng][1], bl[ng][2], bl[ng][3]);
            }
#pragma unroll
            for (int mf = 0; mf < 2; mf++)
#pragma unroll
                for (int nf = 0; nf < 8; nf++) {
                    uint32_t fh[2] = {bh[nf >> 1][(nf & 1) * 2],
                                      bh[nf >> 1][(nf & 1) * 2 + 1]};
                    uint32_t fl[2] = {bl[nf >> 1][(nf & 1) * 2],
                                      bl[nf >> 1][(nf & 1) * 2 + 1]};
                    mma16816(acc[mf][nf], ah[mf], fh);
                    mma16816(acc[mf][nf], ah[mf], fl);
                    mma16816(acc[mf][nf], al[mf], fh);
                }
        }
    }

    // Epilogue
#pragma unroll
    for (int mf = 0; mf < 2; mf++) {
        int mg0 = m0 + wm * 32 + mf * 16 + (lane >> 2);
#pragma unroll
        for (int nf = 0; nf < 8; nf++) {
            int ng = n0 + wn * 64 + nf * 8 + (lane & 3) * 2;
            float b0v = bias[ng], b1v = bias[ng + 1];
#pragma unroll
            for (int half = 0; half < 2; half++) {
                int m = mg0 + half * 8;
                float v0 = acc[mf][nf][half * 2] + b0v;
                float v1 = acc[mf][nf][half * 2 + 1] + b1v;
                if (MODE == 0) {
                    int bb = m >> 11, t = m & 2047, h = ng >> 6, d = ng & 63;
                    size_t o = (((size_t)(bb * Hc + h)) * Tc + t) * Dc + d;
                    uint32_t hiw, low;
                    split_pack(v0, v1, hiw, low);
                    *(uint32_t*)((__nv_bfloat16*)outH + o) = hiw;
                    *(uint32_t*)(outL + o) = low;
                } else {
                    float2 v = make_float2(v0, v1);
                    *(float2*)((float*)outH + (size_t)m * Cc + ng) = v;
                }
            }
        }
    }
}

// ---------------------------------------------------------------------------
// Flash attention via mma.sync.
// Grid (Tc/128, B*H). 256 threads (8 warps x 16 query rows = 128 rows/CTA).
// KV tiles 64 rows, double-buffered cp.async, prefetch-then-compute.
// Q staged through the FULL ping buffer (hi: [0,18432), lo: [18432,36864)).
// ---------------------------------------------------------------------------
#define ASR 144u
#define KH_OFF 0u
#define KL_OFF 9216u
#define VH_OFF 18432u
#define VL_OFF 27648u
#define KVBUF 36864u
#define QLO_OFF 18432u              // Q-lo region during Q staging
#define ATTN_SMEM (2u * KVBUF)      // 73728 B

__device__ __forceinline__ void attn_load_kv(
    uint32_t base, int tid, size_t hb, int n0,
    const __nv_bfloat16* __restrict__ Kh, const __nv_bfloat16* __restrict__ Kl,
    const __nv_bfloat16* __restrict__ Vh, const __nv_bfloat16* __restrict__ Vl) {
#pragma unroll
    for (int it = 0; it < 2; it++) {
        int idx = tid + it * 256;          // 0..511
        int row = idx >> 3, seg = idx & 7;
        uint32_t so = (uint32_t)row * ASR + (uint32_t)seg * 16u;
        size_t g = hb + (size_t)(n0 + row) * Dc + seg * 8;
        CPA16(base + KH_OFF + so, Kh + g);
        CPA16(base + KL_OFF + so, Kl + g);
        CPA16(base + VH_OFF + so, Vh + g);
        CPA16(base + VL_OFF + so, Vl + g);
    }
}

__global__ __launch_bounds__(256) void attn_mma(
    const __nv_bfloat16* __restrict__ Qh, const __nv_bfloat16* __restrict__ Ql,
    const __nv_bfloat16* __restrict__ Kh, const __nv_bfloat16* __restrict__ Kl,
    const __nv_bfloat16* __restrict__ Vh, const __nv_bfloat16* __restrict__ Vl,
    __nv_bfloat16* __restrict__ Yh, __nv_bfloat16* __restrict__ Yl) {
    extern __shared__ __align__(16) char sma[];
    const uint32_t sb = cvta_s(sma);
    const int tid = threadIdx.x, lane = tid & 31, wid = tid >> 5;
    const int bh_i = blockIdx.y;
    const int m0 = blockIdx.x * 128;
    const size_t hb = (size_t)bh_i * Tc * Dc;
    const int NT = 2 * blockIdx.x + 2;     // KV tiles for this CTA

    // ---- Stage Q (128 rows): hi fills [0,18432), lo fills [18432,36864) ----
#pragma unroll
    for (int it = 0; it < 4; it++) {
        int idx = tid + it * 256;          // 0..1023
        int row = idx >> 3, seg = idx & 7; // row 0..127
        uint32_t so = (uint32_t)row * ASR + (uint32_t)seg * 16u;
        size_t g = hb + (size_t)(m0 + row) * Dc + seg * 8;
        CPA16(sb + so, Qh + g);
        CPA16(sb + QLO_OFF + so, Ql + g);
    }
    CPCOMMIT();
    CPWAIT(0);
    __syncthreads();

    uint32_t qfh[4][4], qfl[4][4];
    {
        const int arow = wid * 16 + (lane & 15);   // 0..127
        const int akof = (lane >> 4) << 3;
#pragma unroll
        for (int kf = 0; kf < 4; kf++) {
            uint32_t ao = (uint32_t)arow * ASR + (uint32_t)(kf * 16 + akof) * 2u;
            ldsm4(sb + ao, qfh[kf][0], qfh[kf][1], qfh[kf][2], qfh[kf][3]);
            ldsm4(sb + QLO_OFF + ao, qfl[kf][0], qfl[kf][1], qfl[kf][2], qfl[kf][3]);
        }
    }
    __syncthreads();    // Q staging fully read; buffer 0 reusable

    attn_load_kv(sb, tid, hb, 0, Kh, Kl, Vh, Vl);
    CPCOMMIT();

    float oacc[8][4];
#pragma unroll
    for (int i = 0; i < 8; i++)
#pragma unroll
        for (int j = 0; j < 4; j++) oacc[i][j] = 0.0f;
    float rm[2] = {-1e30f, -1e30f};
    float rs[2] = {0.0f, 0.0f};

    const int brow = (lane & 7) + ((lane & 16) >> 1);
    const int bkof = lane & 8;
    const float sc = 0.125f;
    const int wrow0 = m0 + wid * 16;

    for (int nt = 0; nt < NT; nt++) {
        const int n0 = nt * 64;
        CPWAIT(0);
        __syncthreads();          // tile nt visible; compute(nt-1) done by all
        if (nt + 1 < NT) {
            attn_load_kv(sb + (uint32_t)((nt + 1) & 1) * KVBUF, tid, hb,
                         (nt + 1) * 64, Kh, Kl, Vh, Vl);
            CPCOMMIT();
        }
        const uint32_t base = sb + (uint32_t)(nt & 1) * KVBUF;

        // ---- S = Q K^T (3-term split) ----
        float s[8][4];
#pragma unroll
        for (int i = 0; i < 8; i++)
#pragma unroll
            for (int j = 0; j < 4; j++) s[i][j] = 0.0f;
#pragma unroll
        for (int kf = 0; kf < 4; kf++) {
            uint32_t kfh[4][4], kfl[4][4];
            const uint32_t bcb = (uint32_t)(kf * 16 + bkof) * 2u;
#pragma unroll
            for (int ng = 0; ng < 4; ng++) {
                uint32_t bo = (uint32_t)(ng * 16 + brow) * ASR + bcb;
                ldsm4(base + KH_OFF + bo, kfh[ng][0], kfh[ng][1], kfh[ng][2], kfh[ng][3]);
                ldsm4(base + KL_OFF + bo, kfl[ng][0], kfl[ng][1], kfl[ng][2], kfl[ng][3]);
            }
#pragma unroll
            for (int nf = 0; nf < 8; nf++) {
                uint32_t fh[2] = {kfh[nf >> 1][(nf & 1) * 2],
                                  kfh[nf >> 1][(nf & 1) * 2 + 1]};
                uint32_t fl[2] = {kfl[nf >> 1][(nf & 1) * 2],
                                  kfl[nf >> 1][(nf & 1) * 2 + 1]};
                mma16816(s[nf], qfh[kf], fh);
                mma16816(s[nf], qfh[kf], fl);
                mma16816(s[nf], qfl[kf], fh);
            }
        }

        // ---- scale + causal mask (per-warp: only diagonal region masks) ----
        if (n0 + 63 > wrow0) {
            const int r0 = wrow0 + (lane >> 2);
#pragma unroll
            for (int nf = 0; nf < 8; nf++) {
                const int c0 = n0 + nf * 8 + (lane & 3) * 2;
#pragma unroll
                for (int half = 0; half < 2; half++) {
                    const int row = r0 + half * 8;
                    s[nf][half * 2]     = (c0     <= row) ? s[nf][half * 2] * sc     : -1e30f;
                    s[nf][half * 2 + 1] = (c0 + 1 <= row) ? s[nf][half * 2 + 1] * sc : -1e30f;
                }
            }
        } else {
#pragma unroll
            for (int nf = 0; nf < 8; nf++)
#pragma unroll
                for (int j = 0; j < 4; j++) s[nf][j] *= sc;
        }

        // ---- online softmax (2 rows per thread) ----
        float tmax[2] = {-1e30f, -1e30f};
#pragma unroll
        for (int nf = 0; nf < 8; nf++) {
            tmax[0] = fmaxf(tmax[0], fmaxf(s[nf][0], s[nf][1]));
            tmax[1] = fmaxf(tmax[1], fmaxf(s[nf][2], s[nf][3]));
        }
#pragma unroll
        for (int h = 0; h < 2; h++) {
            tmax[h] = fmaxf(tmax[h], __shfl_xor_sync(0xffffffffu, tmax[h], 1));
            tmax[h] = fmaxf(tmax[h], __shfl_xor_sync(0xffffffffu, tmax[h], 2));
        }
        float nm0 = fmaxf(rm[0], tmax[0]);
        float nm1 = fmaxf(rm[1], tmax[1]);
        float corr0 = __expf(rm[0] - nm0);
        float corr1 = __expf(rm[1] - nm1);
        rm[0] = nm0; rm[1] = nm1;
        float ts0 = 0.0f, ts1 = 0.0f;
#pragma unroll
        for (int nf = 0; nf < 8; nf++) {
            s[nf][0] = __expf(s[nf][0] - nm0); ts0 += s[nf][0];
            s[nf][1] = __expf(s[nf][1] - nm0); ts0 += s[nf][1];
            s[nf][2] = __expf(s[nf][2] - nm1); ts1 += s[nf][2];
            s[nf][3] = __expf(s[nf][3] - nm1); ts1 += s[nf][3];
        }
        ts0 += __shfl_xor_sync(0xffffffffu, ts0, 1);
        ts0 += __shfl_xor_sync(0xffffffffu, ts0, 2);
        ts1 += __shfl_xor_sync(0xffffffffu, ts1, 1);
        ts1 += __shfl_xor_sync(0xffffffffu, ts1, 2);
        rs[0] = rs[0] * corr0 + ts0;
        rs[1] = rs[1] * corr1 + ts1;
#pragma unroll
        for (int df = 0; df < 8; df++) {
            oacc[df][0] *= corr0; oacc[df][1] *= corr0;
            oacc[df][2] *= corr1; oacc[df][3] *= corr1;
        }

        // ---- P frags (hi/lo) ----
        uint32_t pfh[4][4], pfl[4][4];
#pragma unroll
        for (int kf2 = 0; kf2 < 4; kf2++) {
            split_pack(s[2 * kf2][0], s[2 * kf2][1], pfh[kf2][0], pfl[kf2][0]);
            split_pack(s[2 * kf2][2], s[2 * kf2][3], pfh[kf2][1], pfl[kf2][1]);
            split_pack(s[2 * kf2 + 1][0], s[2 * kf2 + 1][1], pfh[kf2][2], pfl[kf2][2]);
            split_pack(s[2 * kf2 + 1][2], s[2 * kf2 + 1][3], pfh[kf2][3], pfl[kf2][3]);
        }

        // ---- O += P V (3-term) ----
#pragma unroll
        for (int df = 0; df < 8; df++) {
#pragma unroll
            for (int kf2 = 0; kf2 < 4; kf2++) {
                uint32_t vo = (uint32_t)(kf2 * 16 + (lane & 15)) * ASR +
                              (uint32_t)df * 16u;
                uint32_t vb[2], vlb[2];
                ldsm2t(base + VH_OFF + vo, vb[0], vb[1]);
                ldsm2t(base + VL_OFF + vo, vlb[0], vlb[1]);
                mma16816(oacc[df], pfh[kf2], vb);
                mma16816(oacc[df], pfh[kf2], vlb);
                mma16816(oacc[df], pfl[kf2], vb);
            }
        }
    }

    // ---- epilogue ----
    const float inv0 = 1.0f / rs[0];
    const float inv1 = 1.0f / rs[1];
    const int b = bh_i >> 4, h = bh_i & 15;
    const int t0 = m0 + wid * 16 + (lane >> 2);
#pragma unroll
    for (int df = 0; df < 8; df++) {
        const int d = df * 8 + (lane & 3) * 2;
#pragma unroll
        for (int half = 0; half < 2; half++) {
            const int t = t0 + half * 8;
            const float inv = half ? inv1 : inv0;
            float v0 = oacc[df][half * 2] * inv;
            float v1 = oacc[df][half * 2 + 1] * inv;
            uint32_t hiw, low;
            split_pack(v0, v1, hiw, low);
            size_t o = ((size_t)(b * Tc + t)) * Cc + h * Dc + d;
            *(uint32_t*)(Yh + o) = hiw;
            *(uint32_t*)(Yl + o) = low;
        }
    }
}

// ---------------------------------------------------------------------------
extern "C" void kernel_launch(void* const* d_in, const int* in_sizes, int n_in,
                              void* d_out, int out_size) {
    const float* x  = (const float*)d_in[0];
    const float* Wk = (const float*)d_in[1];
    const float* bk = (const float*)d_in[2];
    const float* Wq = (const float*)d_in[3];
    const float* bq = (const float*)d_in[4];
    const float* Wv = (const float*)d_in[5];
    const float* bv = (const float*)d_in[6];
    const float* Wp = (const float*)d_in[7];
    const float* bp = (const float*)d_in[8];
    float* out = (float*)d_out;

    __nv_bfloat16 *xh, *xl, *yh, *yl;
    __nv_bfloat16 *qh, *ql, *kh, *kl, *vh, *vl;
    __nv_bfloat16 *wqh, *wql, *wkh, *wkl, *wvh, *wvl, *wph, *wpl;
    cudaGetSymbolAddress((void**)&xh, g_xh);
    cudaGetSymbolAddress((void**)&xl, g_xl);
    cudaGetSymbolAddress((void**)&yh, g_yh);
    cudaGetSymbolAddress((void**)&yl, g_yl);
    cudaGetSymbolAddress((void**)&qh, g_qh);
    cudaGetSymbolAddress((void**)&ql, g_ql);
    cudaGetSymbolAddress((void**)&kh, g_kh);
    cudaGetSymbolAddress((void**)&kl, g_kl);
    cudaGetSymbolAddress((void**)&vh, g_vh);
    cudaGetSymbolAddress((void**)&vl, g_vl);
    cudaGetSymbolAddress((void**)&wqh, g_wqh);
    cudaGetSymbolAddress((void**)&wql, g_wql);
    cudaGetSymbolAddress((void**)&wkh, g_wkh);
    cudaGetSymbolAddress((void**)&wkl, g_wkl);
    cudaGetSymbolAddress((void**)&wvh, g_wvh);
    cudaGetSymbolAddress((void**)&wvl, g_wvl);
    cudaGetSymbolAddress((void**)&wph, g_wph);
    cudaGetSymbolAddress((void**)&wpl, g_wpl);

    cudaFuncSetAttribute(gemm_mma<0>, cudaFuncAttributeMaxDynamicSharedMemorySize,
                         (int)GEMM_SMEM);
    cudaFuncSetAttribute(gemm_mma<1>, cudaFuncAttributeMaxDynamicSharedMemorySize,
                         (int)GEMM_SMEM);
    cudaFuncSetAttribute(attn_mma, cudaFuncAttributeMaxDynamicSharedMemorySize,
                         (int)ATTN_SMEM);

    split_bf16<<<Mtot * Cc / 4 / 256, 256>>>(x, xh, xl);
    split_bf16<<<Cc * Cc / 4 / 256, 256>>>(Wq, wqh, wql);
    split_bf16<<<Cc * Cc / 4 / 256, 256>>>(Wk, wkh, wkl);
    split_bf16<<<Cc * Cc / 4 / 256, 256>>>(Wv, wvh, wvl);
    split_bf16<<<Cc * Cc / 4 / 256, 256>>>(Wp, wph, wpl);

    dim3 ggrid(Cc / 128, Mtot / 128);   // (8, 32)
    gemm_mma<0><<<ggrid, 256, GEMM_SMEM>>>(xh, xl, wqh, wql, bq, qh, ql);
    gemm_mma<0><<<ggrid, 256, GEMM_SMEM>>>(xh, xl, wkh, wkl, bk, kh, kl);
    gemm_mma<0><<<ggrid, 256, GEMM_SMEM>>>(xh, xl, wvh, wvl, bv, vh, vl);

    dim3 agrid(Tc / 128, BHc);          // (16, 32)
    attn_mma<<<agrid, 256, ATTN_SMEM>>>(qh, ql, kh, kl, vh, vl, yh, yl);

    gemm_mma<1><<<ggrid, 256, GEMM_SMEM>>>(yh, yl, wph, wpl, bp, out, nullptr);
}

// round 11
// speedup vs baseline: 1.0828x; 1.0828x over previous
#include <cuda_runtime.h>
#include <cuda_bf16.h>
#include <cstdint>

// Problem constants
#define Bc 2
#define Tc 2048
#define Cc 1024
#define Hc 16
#define Dc 64
#define Mtot 4096
#define BHc 32

// ---------------------------------------------------------------------------
// Scratch (__device__ globals)
// ---------------------------------------------------------------------------
__device__ __align__(256) __nv_bfloat16 g_xh[Mtot * Cc];
__device__ __align__(256) __nv_bfloat16 g_xl[Mtot * Cc];
__device__ __align__(256) __nv_bfloat16 g_qh[BHc * Tc * Dc];
__device__ __align__(256) __nv_bfloat16 g_ql[BHc * Tc * Dc];
__device__ __align__(256) __nv_bfloat16 g_kh[BHc * Tc * Dc];
__device__ __align__(256) __nv_bfloat16 g_kl[BHc * Tc * Dc];
__device__ __align__(256) __nv_bfloat16 g_vh[BHc * Tc * Dc];
__device__ __align__(256) __nv_bfloat16 g_vl[BHc * Tc * Dc];
__device__ __align__(256) __nv_bfloat16 g_yh[Mtot * Cc];
__device__ __align__(256) __nv_bfloat16 g_yl[Mtot * Cc];
__device__ __align__(256) __nv_bfloat16 g_wqh[Cc * Cc];
__device__ __align__(256) __nv_bfloat16 g_wql[Cc * Cc];
__device__ __align__(256) __nv_bfloat16 g_wkh[Cc * Cc];
__device__ __align__(256) __nv_bfloat16 g_wkl[Cc * Cc];
__device__ __align__(256) __nv_bfloat16 g_wvh[Cc * Cc];
__device__ __align__(256) __nv_bfloat16 g_wvl[Cc * Cc];
__device__ __align__(256) __nv_bfloat16 g_wph[Cc * Cc];
__device__ __align__(256) __nv_bfloat16 g_wpl[Cc * Cc];

// ---------------------------------------------------------------------------
// Baseline-PTX helpers (sm_103-safe)
// ---------------------------------------------------------------------------
__device__ __forceinline__ uint32_t cvta_s(const void* p) {
    return (uint32_t)__cvta_generic_to_shared(p);
}
__device__ __forceinline__ void ldsm4(uint32_t a, uint32_t& r0, uint32_t& r1,
                                      uint32_t& r2, uint32_t& r3) {
    asm volatile("ldmatrix.sync.aligned.m8n8.x4.shared.b16 {%0,%1,%2,%3}, [%4];"
                 : "=r"(r0), "=r"(r1), "=r"(r2), "=r"(r3) : "r"(a));
}
__device__ __forceinline__ void ldsm2t(uint32_t a, uint32_t& r0, uint32_t& r1) {
    asm volatile("ldmatrix.sync.aligned.m8n8.x2.trans.shared.b16 {%0,%1}, [%2];"
                 : "=r"(r0), "=r"(r1) : "r"(a));
}
__device__ __forceinline__ void mma16816(float* d, const uint32_t* a,
                                         const uint32_t* b) {
    asm volatile(
        "mma.sync.aligned.m16n8k16.row.col.f32.bf16.bf16.f32 "
        "{%0,%1,%2,%3}, {%4,%5,%6,%7}, {%8,%9}, {%0,%1,%2,%3};"
        : "+f"(d[0]), "+f"(d[1]), "+f"(d[2]), "+f"(d[3])
        : "r"(a[0]), "r"(a[1]), "r"(a[2]), "r"(a[3]), "r"(b[0]), "r"(b[1]));
}
#define CPA16(s, g) \
    asm volatile("cp.async.cg.shared.global [%0], [%1], 16;" :: "r"(s), "l"(g))
#define CPCOMMIT() asm volatile("cp.async.commit_group;" ::: "memory")
#define CPWAIT(n)  asm volatile("cp.async.wait_group %0;" :: "n"(n) : "memory")

__device__ __forceinline__ uint32_t pack_bf(__nv_bfloat16 a, __nv_bfloat16 b) {
    __nv_bfloat162 t = __halves2bfloat162(a, b);
    return *reinterpret_cast<uint32_t*>(&t);
}
__device__ __forceinline__ void split_pack(float e, float o, uint32_t& hi,
                                           uint32_t& lo) {
    __nv_bfloat16 he = __float2bfloat16_rn(e);
    __nv_bfloat16 ho = __float2bfloat16_rn(o);
    __nv_bfloat16 le = __float2bfloat16_rn(e - __bfloat162float(he));
    __nv_bfloat16 lo_ = __float2bfloat16_rn(o - __bfloat162float(ho));
    hi = pack_bf(he, ho);
    lo = pack_bf(le, lo_);
}

// ---------------------------------------------------------------------------
// fp32 -> (hi, lo) bf16 split
// ---------------------------------------------------------------------------
__global__ __launch_bounds__(256) void split_bf16(const float* __restrict__ src,
                                                  __nv_bfloat16* __restrict__ hi,
                                                  __nv_bfloat16* __restrict__ lo) {
    int i = blockIdx.x * blockDim.x + threadIdx.x;
    float4 v = ((const float4*)src)[i];
    __nv_bfloat16 h0 = __float2bfloat16_rn(v.x);
    __nv_bfloat16 h1 = __float2bfloat16_rn(v.y);
    __nv_bfloat16 h2 = __float2bfloat16_rn(v.z);
    __nv_bfloat16 h3 = __float2bfloat16_rn(v.w);
    __nv_bfloat16 l0 = __float2bfloat16_rn(v.x - __bfloat162float(h0));
    __nv_bfloat16 l1 = __float2bfloat16_rn(v.y - __bfloat162float(h1));
    __nv_bfloat16 l2 = __float2bfloat16_rn(v.z - __bfloat162float(h2));
    __nv_bfloat16 l3 = __float2bfloat16_rn(v.w - __bfloat162float(h3));
    ((__nv_bfloat162*)hi)[2 * i]     = __halves2bfloat162(h0, h1);
    ((__nv_bfloat162*)hi)[2 * i + 1] = __halves2bfloat162(h2, h3);
    ((__nv_bfloat162*)lo)[2 * i]     = __halves2bfloat162(l0, l1);
    ((__nv_bfloat162*)lo)[2 * i + 1] = __halves2bfloat162(l2, l3);
}

// ---------------------------------------------------------------------------
// GEMM via mma.sync: out = (Ah+Al) @ (Bh+Bl)^T + bias
// CTA 128x128, 8 warps (warp tile 32x64), BK=32.
// 2-stage cp.async pipeline, ONE __syncthreads per K-tile (prefetch kt+1
// after the barrier — every warp has finished computing kt-1, so the target
// buffer is free; CPWAIT(0) only drains the already-overlapped tile kt).
// smem 81920 B -> 2 CTAs/SM.
// ---------------------------------------------------------------------------
#define SRB 80u
#define MATB (128u * SRB)
#define STAGEB (4u * MATB)          // 40960 B
#define GEMM_SMEM (2u * STAGEB)     // 81920 B
#define GNT (Cc / 32)               // 32 K-tiles

__device__ __forceinline__ void gemm_load_stage(
    uint32_t base, int tid, int m0, int n0, int k0,
    const __nv_bfloat16* __restrict__ Ah, const __nv_bfloat16* __restrict__ Al,
    const __nv_bfloat16* __restrict__ Bh, const __nv_bfloat16* __restrict__ Bl) {
#pragma unroll
    for (int it = 0; it < 2; it++) {
        int idx = tid + it * 256;
        int row = idx >> 2, seg = idx & 3;
        uint32_t so = (uint32_t)row * SRB + (uint32_t)seg * 16u;
        size_t ga = (size_t)(m0 + row) * Cc + k0 + seg * 8;
        size_t gb = (size_t)(n0 + row) * Cc + k0 + seg * 8;
        CPA16(base + so, Ah + ga);
        CPA16(base + MATB + so, Al + ga);
        CPA16(base + 2u * MATB + so, Bh + gb);
        CPA16(base + 3u * MATB + so, Bl + gb);
    }
}

template <int MODE>
__global__ __launch_bounds__(256) void gemm_mma(
    const __nv_bfloat16* __restrict__ Ah, const __nv_bfloat16* __restrict__ Al,
    const __nv_bfloat16* __restrict__ Bh, const __nv_bfloat16* __restrict__ Bl,
    const float* __restrict__ bias,
    void* __restrict__ outH, __nv_bfloat16* __restrict__ outL) {
    extern __shared__ __align__(16) char smg[];
    const uint32_t sb = cvta_s(smg);
    const int tid = threadIdx.x, lane = tid & 31, wid = tid >> 5;
    const int wm = wid & 3, wn = wid >> 2;
    const int m0 = blockIdx.y * 128, n0 = blockIdx.x * 128;

    float acc[2][8][4];
#pragma unroll
    for (int i = 0; i < 2; i++)
#pragma unroll
        for (int j = 0; j < 8; j++)
#pragma unroll
            for (int k = 0; k < 4; k++) acc[i][j][k] = 0.0f;

    gemm_load_stage(sb, tid, m0, n0, 0, Ah, Al, Bh, Bl);
    CPCOMMIT();

    const int arow = wm * 32 + (lane & 15);
    const int akof = (lane >> 4) << 3;
    const int brow = (lane & 7) + ((lane & 16) >> 1);
    const int bkof = lane & 8;

    for (int kt = 0; kt < GNT; kt++) {
        CPWAIT(0);
        __syncthreads();
        if (kt + 1 < GNT) {
            gemm_load_stage(sb + (uint32_t)((kt + 1) & 1) * STAGEB, tid, m0, n0,
                            (kt + 1) * 32, Ah, Al, Bh, Bl);
            CPCOMMIT();
        }
        const uint32_t base = sb + (uint32_t)(kt & 1) * STAGEB;
#pragma unroll
        for (int ks = 0; ks < 2; ks++) {
            uint32_t ah[2][4], al[2][4];
            const uint32_t acb = (uint32_t)(ks * 16 + akof) * 2u;
#pragma unroll
            for (int mf = 0; mf < 2; mf++) {
                uint32_t ao = (uint32_t)(arow + mf * 16) * SRB + acb;
                ldsm4(base + ao, ah[mf][0], ah[mf][1], ah[mf][2], ah[mf][3]);
                ldsm4(base + MATB + ao, al[mf][0], al[mf][1], al[mf][2], al[mf][3]);
            }
            uint32_t bh[4][4], bl[4][4];
            const uint32_t bcb = (uint32_t)(ks * 16 + bkof) * 2u;
#pragma unroll
            for (int ng = 0; ng < 4; ng++) {
                uint32_t bo = (uint32_t)(wn * 64 + ng * 16 + brow) * SRB + bcb;
                ldsm4(base + 2u * MATB + bo, bh[ng][0], bh[ng][1], bh[ng][2], bh[ng][3]);
                ldsm4(base + 3u * MATB + bo, bl[ng][0], bl[ng][1], bl[ng][2], bl[ng][3]);
            }
#pragma unroll
            for (int mf = 0; mf < 2; mf++)
#pragma unroll
                for (int nf = 0; nf < 8; nf++) {
                    uint32_t fh[2] = {bh[nf >> 1][(nf & 1) * 2],
                                      bh[nf >> 1][(nf & 1) * 2 + 1]};
                    uint32_t fl[2] = {bl[nf >> 1][(nf & 1) * 2],
                                      bl[nf >> 1][(nf & 1) * 2 + 1]};
                    mma16816(acc[mf][nf], ah[mf], fh);
                    mma16816(acc[mf][nf], ah[mf], fl);
                    mma16816(acc[mf][nf], al[mf], fh);
                }
        }
    }

    // Epilogue
#pragma unroll
    for (int mf = 0; mf < 2; mf++) {
        int mg0 = m0 + wm * 32 + mf * 16 + (lane >> 2);
#pragma unroll
        for (int nf = 0; nf < 8; nf++) {
            int ng = n0 + wn * 64 + nf * 8 + (lane & 3) * 2;
            float b0v = bias[ng], b1v = bias[ng + 1];
#pragma unroll
            for (int half = 0; half < 2; half++) {
                int m = mg0 + half * 8;
                float v0 = acc[mf][nf][half * 2] + b0v;
                float v1 = acc[mf][nf][half * 2 + 1] + b1v;
                if (MODE == 0) {
                    int bb = m >> 11, t = m & 2047, h = ng >> 6, d = ng & 63;
                    size_t o = (((size_t)(bb * Hc + h)) * Tc + t) * Dc + d;
                    uint32_t hiw, low;
                    split_pack(v0, v1, hiw, low);
                    *(uint32_t*)((__nv_bfloat16*)outH + o) = hiw;
                    *(uint32_t*)(outL + o) = low;
                } else {
                    float2 v = make_float2(v0, v1);
                    *(float2*)((float*)outH + (size_t)m * Cc + ng) = v;
                }
            }
        }
    }
}

// ---------------------------------------------------------------------------
// Flash attention via mma.sync. Grid (T/64, B*H). 128 threads (4 warps,
// each warp owns 16 query rows). Q frags resident. KV tiles 64x64 hi/lo,
// DOUBLE-buffered cp.async with the single-barrier prefetch-then-compute
// loop. smem 73728 B; 128-thread CTAs stay 2/SM on registers.
// ---------------------------------------------------------------------------
#define ASR 144u
#define KH_OFF 0u
#define KL_OFF 9216u
#define VH_OFF 18432u
#define VL_OFF 27648u
#define KVBUF 36864u
#define ATTN_SMEM (2u * KVBUF)      // 73728 B

__device__ __forceinline__ void attn_load_kv(
    uint32_t base, int tid, size_t hb, int n0,
    const __nv_bfloat16* __restrict__ Kh, const __nv_bfloat16* __restrict__ Kl,
    const __nv_bfloat16* __restrict__ Vh, const __nv_bfloat16* __restrict__ Vl) {
#pragma unroll
    for (int it = 0; it < 4; it++) {
        int idx = tid + it * 128;          // 0..511
        int row = idx >> 3, seg = idx & 7; // row 0..63
        uint32_t so = (uint32_t)row * ASR + (uint32_t)seg * 16u;
        size_t g = hb + (size_t)(n0 + row) * Dc + seg * 8;
        CPA16(base + KH_OFF + so, Kh + g);
        CPA16(base + KL_OFF + so, Kl + g);
        CPA16(base + VH_OFF + so, Vh + g);
        CPA16(base + VL_OFF + so, Vl + g);
    }
}

__global__ __launch_bounds__(128) void attn_mma(
    const __nv_bfloat16* __restrict__ Qh, const __nv_bfloat16* __restrict__ Ql,
    const __nv_bfloat16* __restrict__ Kh, const __nv_bfloat16* __restrict__ Kl,
    const __nv_bfloat16* __restrict__ Vh, const __nv_bfloat16* __restrict__ Vl,
    __nv_bfloat16* __restrict__ Yh, __nv_bfloat16* __restrict__ Yl) {
    extern __shared__ __align__(16) char sma[];
    const uint32_t sb = cvta_s(sma);
    const int tid = threadIdx.x, lane = tid & 31, wid = tid >> 5;
    const int bh_i = blockIdx.y;
    const int m0 = blockIdx.x * 64;
    const size_t hb = (size_t)bh_i * Tc * Dc;
    const int NT = blockIdx.x + 1;         // 64-row KV tiles for this CTA

    // ---- Stage Q (64 rows) into buffer 0, pull frags, then release ----
#pragma unroll
    for (int it = 0; it < 4; it++) {
        int idx = tid + it * 128;          // 0..511
        int row = idx >> 3, seg = idx & 7;
        uint32_t so = (uint32_t)row * ASR + (uint32_t)seg * 16u;
        size_t g = hb + (size_t)(m0 + row) * Dc + seg * 8;
        CPA16(sb + KH_OFF + so, Qh + g);
        CPA16(sb + KL_OFF + so, Ql + g);
    }
    CPCOMMIT();
    CPWAIT(0);
    __syncthreads();

    uint32_t qfh[4][4], qfl[4][4];
    {
        const int arow = wid * 16 + (lane & 15);
        const int akof = (lane >> 4) << 3;
#pragma unroll
        for (int kf = 0; kf < 4; kf++) {
            uint32_t ao = (uint32_t)arow * ASR + (uint32_t)(kf * 16 + akof) * 2u;
            ldsm4(sb + KH_OFF + ao, qfh[kf][0], qfh[kf][1], qfh[kf][2], qfh[kf][3]);
            ldsm4(sb + KL_OFF + ao, qfl[kf][0], qfl[kf][1], qfl[kf][2], qfl[kf][3]);
        }
    }
    __syncthreads();    // Q staging fully read; buffer 0 reusable

    attn_load_kv(sb, tid, hb, 0, Kh, Kl, Vh, Vl);
    CPCOMMIT();

    float oacc[8][4];
#pragma unroll
    for (int i = 0; i < 8; i++)
#pragma unroll
        for (int j = 0; j < 4; j++) oacc[i][j] = 0.0f;
    float rm[2] = {-1e30f, -1e30f};
    float rs[2] = {0.0f, 0.0f};

    const int brow = (lane & 7) + ((lane & 16) >> 1);
    const int bkof = lane & 8;
    const float sc = 0.125f;

    for (int nt = 0; nt < NT; nt++) {
        const int n0 = nt * 64;
        CPWAIT(0);
        __syncthreads();          // tile nt visible; compute(nt-1) done by all
        if (nt + 1 < NT) {
            attn_load_kv(sb + (uint32_t)((nt + 1) & 1) * KVBUF, tid, hb,
                         (nt + 1) * 64, Kh, Kl, Vh, Vl);
            CPCOMMIT();
        }
        const uint32_t base = sb + (uint32_t)(nt & 1) * KVBUF;

        // ---- S = Q K^T (3-term split) ----
        float s[8][4];
#pragma unroll
        for (int i = 0; i < 8; i++)
#pragma unroll
            for (int j = 0; j < 4; j++) s[i][j] = 0.0f;
#pragma unroll
        for (int kf = 0; kf < 4; kf++) {
            uint32_t kfh[4][4], kfl[4][4];
            const uint32_t bcb = (uint32_t)(kf * 16 + bkof) * 2u;
#pragma unroll
            for (int ng = 0; ng < 4; ng++) {
                uint32_t bo = (uint32_t)(ng * 16 + brow) * ASR + bcb;
                ldsm4(base + KH_OFF + bo, kfh[ng][0], kfh[ng][1], kfh[ng][2], kfh[ng][3]);
                ldsm4(base + KL_OFF + bo, kfl[ng][0], kfl[ng][1], kfl[ng][2], kfl[ng][3]);
            }
#pragma unroll
            for (int nf = 0; nf < 8; nf++) {
                uint32_t fh[2] = {kfh[nf >> 1][(nf & 1) * 2],
                                  kfh[nf >> 1][(nf & 1) * 2 + 1]};
                uint32_t fl[2] = {kfl[nf >> 1][(nf & 1) * 2],
                                  kfl[nf >> 1][(nf & 1) * 2 + 1]};
                mma16816(s[nf], qfh[kf], fh);
                mma16816(s[nf], qfh[kf], fl);
                mma16816(s[nf], qfl[kf], fh);
            }
        }

        // ---- scale + causal mask (only the diagonal tile masks) ----
        if (n0 == m0) {
            const int r0 = m0 + wid * 16 + (lane >> 2);
#pragma unroll
            for (int nf = 0; nf < 8; nf++) {
                const int c0 = n0 + nf * 8 + (lane & 3) * 2;
#pragma unroll
                for (int half = 0; half < 2; half++) {
                    const int row = r0 + half * 8;
                    s[nf][half * 2]     = (c0     <= row) ? s[nf][half * 2] * sc     : -1e30f;
                    s[nf][half * 2 + 1] = (c0 + 1 <= row) ? s[nf][half * 2 + 1] * sc : -1e30f;
                }
            }
        } else {
#pragma unroll
            for (int nf = 0; nf < 8; nf++)
#pragma unroll
                for (int j = 0; j < 4; j++) s[nf][j] *= sc;
        }

        // ---- online softmax (2 rows per thread) ----
        float tmax[2] = {-1e30f, -1e30f};
#pragma unroll
        for (int nf = 0; nf < 8; nf++) {
            tmax[0] = fmaxf(tmax[0], fmaxf(s[nf][0], s[nf][1]));
            tmax[1] = fmaxf(tmax[1], fmaxf(s[nf][2], s[nf][3]));
        }
#pragma unroll
        for (int h = 0; h < 2; h++) {
            tmax[h] = fmaxf(tmax[h], __shfl_xor_sync(0xffffffffu, tmax[h], 1));
            tmax[h] = fmaxf(tmax[h], __shfl_xor_sync(0xffffffffu, tmax[h], 2));
        }
        float nm0 = fmaxf(rm[0], tmax[0]);
        float nm1 = fmaxf(rm[1], tmax[1]);
        float corr0 = __expf(rm[0] - nm0);
        float corr1 = __expf(rm[1] - nm1);
        rm[0] = nm0; rm[1] = nm1;
        float ts0 = 0.0f, ts1 = 0.0f;
#pragma unroll
        for (int nf = 0; nf < 8; nf++) {
            s[nf][0] = __expf(s[nf][0] - nm0); ts0 += s[nf][0];
            s[nf][1] = __expf(s[nf][1] - nm0); ts0 += s[nf][1];
            s[nf][2] = __expf(s[nf][2] - nm1); ts1 += s[nf][2];
            s[nf][3] = __expf(s[nf][3] - nm1); ts1 += s[nf][3];
        }
        ts0 += __shfl_xor_sync(0xffffffffu, ts0, 1);
        ts0 += __shfl_xor_sync(0xffffffffu, ts0, 2);
        ts1 += __shfl_xor_sync(0xffffffffu, ts1, 1);
        ts1 += __shfl_xor_sync(0xffffffffu, ts1, 2);
        rs[0] = rs[0] * corr0 + ts0;
        rs[1] = rs[1] * corr1 + ts1;
#pragma unroll
        for (int df = 0; df < 8; df++) {
            oacc[df][0] *= corr0; oacc[df][1] *= corr0;
            oacc[df][2] *= corr1; oacc[df][3] *= corr1;
        }

        // ---- P frags (hi/lo) ----
        uint32_t pfh[4][4], pfl[4][4];
#pragma unroll
        for (int kf2 = 0; kf2 < 4; kf2++) {
            split_pack(s[2 * kf2][0], s[2 * kf2][1], pfh[kf2][0], pfl[kf2][0]);
            split_pack(s[2 * kf2][2], s[2 * kf2][3], pfh[kf2][1], pfl[kf2][1]);
            split_pack(s[2 * kf2 + 1][0], s[2 * kf2 + 1][1], pfh[kf2][2], pfl[kf2][2]);
            split_pack(s[2 * kf2 + 1][2], s[2 * kf2 + 1][3], pfh[kf2][3], pfl[kf2][3]);
        }

        // ---- O += P V (3-term) ----
#pragma unroll
        for (int df = 0; df < 8; df++) {
#pragma unroll
            for (int kf2 = 0; kf2 < 4; kf2++) {
                uint32_t vo = (uint32_t)(kf2 * 16 + (lane & 15)) * ASR +
                              (uint32_t)df * 16u;
                uint32_t vb[2], vlb[2];
                ldsm2t(base + VH_OFF + vo, vb[0], vb[1]);
                ldsm2t(base + VL_OFF + vo, vlb[0], vlb[1]);
                mma16816(oacc[df], pfh[kf2], vb);
                mma16816(oacc[df], pfh[kf2], vlb);
                mma16816(oacc[df], pfl[kf2], vb);
            }
        }
    }

    // ---- epilogue: normalize, split to bf16 hi/lo, write y [B,T,C] ----
    const float inv0 = 1.0f / rs[0];
    const float inv1 = 1.0f / rs[1];
    const int b = bh_i >> 4, h = bh_i & 15;
    const int t0 = m0 + wid * 16 + (lane >> 2);
#pragma unroll
    for (int df = 0; df < 8; df++) {
        const int d = df * 8 + (lane & 3) * 2;
#pragma unroll
        for (int half = 0; half < 2; half++) {
            const int t = t0 + half * 8;
            const float inv = half ? inv1 : inv0;
            float v0 = oacc[df][half * 2] * inv;
            float v1 = oacc[df][half * 2 + 1] * inv;
            uint32_t hiw, low;
            split_pack(v0, v1, hiw, low);
            size_t o = ((size_t)(b * Tc + t)) * Cc + h * Dc + d;
            *(uint32_t*)(Yh + o) = hiw;
            *(uint32_t*)(Yl + o) = low;
        }
    }
}

// ---------------------------------------------------------------------------
extern "C" void kernel_launch(void* const* d_in, const int* in_sizes, int n_in,
                              void* d_out, int out_size) {
    const float* x  = (const float*)d_in[0];
    const float* Wk = (const float*)d_in[1];
    const float* bk = (const float*)d_in[2];
    const float* Wq = (const float*)d_in[3];
    const float* bq = (const float*)d_in[4];
    const float* Wv = (const float*)d_in[5];
    const float* bv = (const float*)d_in[6];
    const float* Wp = (const float*)d_in[7];
    const float* bp = (const float*)d_in[8];
    float* out = (float*)d_out;

    __nv_bfloat16 *xh, *xl, *yh, *yl;
    __nv_bfloat16 *qh, *ql, *kh, *kl, *vh, *vl;
    __nv_bfloat16 *wqh, *wql, *wkh, *wkl, *wvh, *wvl, *wph, *wpl;
    cudaGetSymbolAddress((void**)&xh, g_xh);
    cudaGetSymbolAddress((void**)&xl, g_xl);
    cudaGetSymbolAddress((void**)&yh, g_yh);
    cudaGetSymbolAddress((void**)&yl, g_yl);
    cudaGetSymbolAddress((void**)&qh, g_qh);
    cudaGetSymbolAddress((void**)&ql, g_ql);
    cudaGetSymbolAddress((void**)&kh, g_kh);
    cudaGetSymbolAddress((void**)&kl, g_kl);
    cudaGetSymbolAddress((void**)&vh, g_vh);
    cudaGetSymbolAddress((void**)&vl, g_vl);
    cudaGetSymbolAddress((void**)&wqh, g_wqh);
    cudaGetSymbolAddress((void**)&wql, g_wql);
    cudaGetSymbolAddress((void**)&wkh, g_wkh);
    cudaGetSymbolAddress((void**)&wkl, g_wkl);
    cudaGetSymbolAddress((void**)&wvh, g_wvh);
    cudaGetSymbolAddress((void**)&wvl, g_wvl);
    cudaGetSymbolAddress((void**)&wph, g_wph);
    cudaGetSymbolAddress((void**)&wpl, g_wpl);

    cudaFuncSetAttribute(gemm_mma<0>, cudaFuncAttributeMaxDynamicSharedMemorySize,
                         (int)GEMM_SMEM);
    cudaFuncSetAttribute(gemm_mma<1>, cudaFuncAttributeMaxDynamicSharedMemorySize,
                         (int)GEMM_SMEM);
    cudaFuncSetAttribute(attn_mma, cudaFuncAttributeMaxDynamicSharedMemorySize,
                         (int)ATTN_SMEM);

    split_bf16<<<Mtot * Cc / 4 / 256, 256>>>(x, xh, xl);
    split_bf16<<<Cc * Cc / 4 / 256, 256>>>(Wq, wqh, wql);
    split_bf16<<<Cc * Cc / 4 / 256, 256>>>(Wk, wkh, wkl);
    split_bf16<<<Cc * Cc / 4 / 256, 256>>>(Wv, wvh, wvl);
    split_bf16<<<Cc * Cc / 4 / 256, 256>>>(Wp, wph, wpl);

    dim3 ggrid(Cc / 128, Mtot / 128);   // (8, 32)
    gemm_mma<0><<<ggrid, 256, GEMM_SMEM>>>(xh, xl, wqh, wql, bq, qh, ql);
    gemm_mma<0><<<ggrid, 256, GEMM_SMEM>>>(xh, xl, wkh, wkl, bk, kh, kl);
    gemm_mma<0><<<ggrid, 256, GEMM_SMEM>>>(xh, xl, wvh, wvl, bv, vh, vl);

    dim3 agrid(Tc / 64, BHc);           // (32, 32)
    attn_mma<<<agrid, 128, ATTN_SMEM>>>(qh, ql, kh, kl, vh, vl, yh, yl);

    gemm_mma<1><<<ggrid, 256, GEMM_SMEM>>>(yh, yl, wph, wpl, bp, out, nullptr);
}

// round 13
// speedup vs baseline: 1.2154x; 1.1225x over previous
#include <cuda_runtime.h>
#include <cuda_bf16.h>
#include <cstdint>

// Problem constants
#define Bc 2
#define Tc 2048
#define Cc 1024
#define Hc 16
#define Dc 64
#define Mtot 4096
#define BHc 32

// ---------------------------------------------------------------------------
// Scratch (__device__ globals)
// ---------------------------------------------------------------------------
__device__ __align__(256) __nv_bfloat16 g_xh[Mtot * Cc];
__device__ __align__(256) __nv_bfloat16 g_xl[Mtot * Cc];
__device__ __align__(256) __nv_bfloat16 g_qh[BHc * Tc * Dc];
__device__ __align__(256) __nv_bfloat16 g_ql[BHc * Tc * Dc];
__device__ __align__(256) __nv_bfloat16 g_kh[BHc * Tc * Dc];
__device__ __align__(256) __nv_bfloat16 g_kl[BHc * Tc * Dc];
__device__ __align__(256) __nv_bfloat16 g_vh[BHc * Tc * Dc];
__device__ __align__(256) __nv_bfloat16 g_vl[BHc * Tc * Dc];
__device__ __align__(256) __nv_bfloat16 g_yh[Mtot * Cc];
__device__ __align__(256) __nv_bfloat16 g_yl[Mtot * Cc];
__device__ __align__(256) __nv_bfloat16 g_wqh[Cc * Cc];
__device__ __align__(256) __nv_bfloat16 g_wql[Cc * Cc];
__device__ __align__(256) __nv_bfloat16 g_wkh[Cc * Cc];
__device__ __align__(256) __nv_bfloat16 g_wkl[Cc * Cc];
__device__ __align__(256) __nv_bfloat16 g_wvh[Cc * Cc];
__device__ __align__(256) __nv_bfloat16 g_wvl[Cc * Cc];
__device__ __align__(256) __nv_bfloat16 g_wph[Cc * Cc];
__device__ __align__(256) __nv_bfloat16 g_wpl[Cc * Cc];

// ---------------------------------------------------------------------------
// Baseline-PTX helpers (sm_103-safe)
// ---------------------------------------------------------------------------
__device__ __forceinline__ uint32_t cvta_s(const void* p) {
    return (uint32_t)__cvta_generic_to_shared(p);
}
__device__ __forceinline__ void ldsm4(uint32_t a, uint32_t& r0, uint32_t& r1,
                                      uint32_t& r2, uint32_t& r3) {
    asm volatile("ldmatrix.sync.aligned.m8n8.x4.shared.b16 {%0,%1,%2,%3}, [%4];"
                 : "=r"(r0), "=r"(r1), "=r"(r2), "=r"(r3) : "r"(a));
}
__device__ __forceinline__ void ldsm2t(uint32_t a, uint32_t& r0, uint32_t& r1) {
    asm volatile("ldmatrix.sync.aligned.m8n8.x2.trans.shared.b16 {%0,%1}, [%2];"
                 : "=r"(r0), "=r"(r1) : "r"(a));
}
__device__ __forceinline__ void mma16816(float* d, const uint32_t* a,
                                         const uint32_t* b) {
    asm volatile(
        "mma.sync.aligned.m16n8k16.row.col.f32.bf16.bf16.f32 "
        "{%0,%1,%2,%3}, {%4,%5,%6,%7}, {%8,%9}, {%0,%1,%2,%3};"
        : "+f"(d[0]), "+f"(d[1]), "+f"(d[2]), "+f"(d[3])
        : "r"(a[0]), "r"(a[1]), "r"(a[2]), "r"(a[3]), "r"(b[0]), "r"(b[1]));
}
#define CPA16(s, g) \
    asm volatile("cp.async.cg.shared.global [%0], [%1], 16;" :: "r"(s), "l"(g))
#define CPCOMMIT() asm volatile("cp.async.commit_group;" ::: "memory")
#define CPWAIT(n)  asm volatile("cp.async.wait_group %0;" :: "n"(n) : "memory")

__device__ __forceinline__ uint32_t pack_bf(__nv_bfloat16 a, __nv_bfloat16 b) {
    __nv_bfloat162 t = __halves2bfloat162(a, b);
    return *reinterpret_cast<uint32_t*>(&t);
}
__device__ __forceinline__ void split_pack(float e, float o, uint32_t& hi,
                                           uint32_t& lo) {
    __nv_bfloat16 he = __float2bfloat16_rn(e);
    __nv_bfloat16 ho = __float2bfloat16_rn(o);
    __nv_bfloat16 le = __float2bfloat16_rn(e - __bfloat162float(he));
    __nv_bfloat16 lo_ = __float2bfloat16_rn(o - __bfloat162float(ho));
    hi = pack_bf(he, ho);
    lo = pack_bf(le, lo_);
}

// ---------------------------------------------------------------------------
// fp32 -> (hi, lo) bf16 split
// ---------------------------------------------------------------------------
__global__ __launch_bounds__(256) void split_bf16(const float* __restrict__ src,
                                                  __nv_bfloat16* __restrict__ hi,
                                                  __nv_bfloat16* __restrict__ lo) {
    int i = blockIdx.x * blockDim.x + threadIdx.x;
    float4 v = ((const float4*)src)[i];
    __nv_bfloat16 h0 = __float2bfloat16_rn(v.x);
    __nv_bfloat16 h1 = __float2bfloat16_rn(v.y);
    __nv_bfloat16 h2 = __float2bfloat16_rn(v.z);
    __nv_bfloat16 h3 = __float2bfloat16_rn(v.w);
    __nv_bfloat16 l0 = __float2bfloat16_rn(v.x - __bfloat162float(h0));
    __nv_bfloat16 l1 = __float2bfloat16_rn(v.y - __bfloat162float(h1));
    __nv_bfloat16 l2 = __float2bfloat16_rn(v.z - __bfloat162float(h2));
    __nv_bfloat16 l3 = __float2bfloat16_rn(v.w - __bfloat162float(h3));
    ((__nv_bfloat162*)hi)[2 * i]     = __halves2bfloat162(h0, h1);
    ((__nv_bfloat162*)hi)[2 * i + 1] = __halves2bfloat162(h2, h3);
    ((__nv_bfloat162*)lo)[2 * i]     = __halves2bfloat162(l0, l1);
    ((__nv_bfloat162*)lo)[2 * i + 1] = __halves2bfloat162(l2, l3);
}

// ---------------------------------------------------------------------------
// GEMM core: CTA 128x128, 8 warps (warp tile 32x64), BK=32.
// 2-stage cp.async pipeline, one __syncthreads per K-tile.
// ---------------------------------------------------------------------------
#define SRB 80u
#define MATB (128u * SRB)
#define STAGEB (4u * MATB)          // 40960 B
#define GEMM_SMEM (2u * STAGEB)     // 81920 B
#define GNT (Cc / 32)               // 32 K-tiles

__device__ __forceinline__ void gemm_load_stage(
    uint32_t base, int tid, int m0, int n0, int k0,
    const __nv_bfloat16* __restrict__ Ah, const __nv_bfloat16* __restrict__ Al,
    const __nv_bfloat16* __restrict__ Bh, const __nv_bfloat16* __restrict__ Bl) {
#pragma unroll
    for (int it = 0; it < 2; it++) {
        int idx = tid + it * 256;
        int row = idx >> 2, seg = idx & 3;
        uint32_t so = (uint32_t)row * SRB + (uint32_t)seg * 16u;
        size_t ga = (size_t)(m0 + row) * Cc + k0 + seg * 8;
        size_t gb = (size_t)(n0 + row) * Cc + k0 + seg * 8;
        CPA16(base + so, Ah + ga);
        CPA16(base + MATB + so, Al + ga);
        CPA16(base + 2u * MATB + so, Bh + gb);
        CPA16(base + 3u * MATB + so, Bl + gb);
    }
}

// Shared mainloop: accumulates the 128x128 tile into acc.
__device__ __forceinline__ void gemm_mainloop(
    uint32_t sb, int tid, int lane, int wm, int wn, int m0, int n0,
    const __nv_bfloat16* __restrict__ Ah, const __nv_bfloat16* __restrict__ Al,
    const __nv_bfloat16* __restrict__ Bh, const __nv_bfloat16* __restrict__ Bl,
    float acc[2][8][4]) {
    gemm_load_stage(sb, tid, m0, n0, 0, Ah, Al, Bh, Bl);
    CPCOMMIT();

    const int arow = wm * 32 + (lane & 15);
    const int akof = (lane >> 4) << 3;
    const int brow = (lane & 7) + ((lane & 16) >> 1);
    const int bkof = lane & 8;

    for (int kt = 0; kt < GNT; kt++) {
        CPWAIT(0);
        __syncthreads();
        if (kt + 1 < GNT) {
            gemm_load_stage(sb + (uint32_t)((kt + 1) & 1) * STAGEB, tid, m0, n0,
                            (kt + 1) * 32, Ah, Al, Bh, Bl);
            CPCOMMIT();
        }
        const uint32_t base = sb + (uint32_t)(kt & 1) * STAGEB;
#pragma unroll
        for (int ks = 0; ks < 2; ks++) {
            uint32_t ah[2][4], al[2][4];
            const uint32_t acb = (uint32_t)(ks * 16 + akof) * 2u;
#pragma unroll
            for (int mf = 0; mf < 2; mf++) {
                uint32_t ao = (uint32_t)(arow + mf * 16) * SRB + acb;
                ldsm4(base + ao, ah[mf][0], ah[mf][1], ah[mf][2], ah[mf][3]);
                ldsm4(base + MATB + ao, al[mf][0], al[mf][1], al[mf][2], al[mf][3]);
            }
            uint32_t bh[4][4], bl[4][4];
            const uint32_t bcb = (uint32_t)(ks * 16 + bkof) * 2u;
#pragma unroll
            for (int ng = 0; ng < 4; ng++) {
                uint32_t bo = (uint32_t)(wn * 64 + ng * 16 + brow) * SRB + bcb;
                ldsm4(base + 2u * MATB + bo, bh[ng][0], bh[ng][1], bh[ng][2], bh[ng][3]);
                ldsm4(base + 3u * MATB + bo, bl[ng][0], bl[ng][1], bl[ng][2], bl[ng][3]);
            }
#pragma unroll
            for (int mf = 0; mf < 2; mf++)
#pragma unroll
                for (int nf = 0; nf < 8; nf++) {
                    uint32_t fh[2] = {bh[nf >> 1][(nf & 1) * 2],
                                      bh[nf >> 1][(nf & 1) * 2 + 1]};
                    uint32_t fl[2] = {bl[nf >> 1][(nf & 1) * 2],
                                      bl[nf >> 1][(nf & 1) * 2 + 1]};
                    mma16816(acc[mf][nf], ah[mf], fh);
                    mma16816(acc[mf][nf], ah[mf], fl);
                    mma16816(acc[mf][nf], al[mf], fh);
                }
        }
    }
}

// ---------------------------------------------------------------------------
// Fused QKV projection GEMM: blockIdx.z in {0,1,2} selects {Q,K,V}.
// One 768-CTA launch instead of 3x256 -> single wave-quantization tail,
// x tiles shared through L2 across z.
// Writes bf16 hi/lo into [B,H,T,D] scratch.
// ---------------------------------------------------------------------------
__global__ __launch_bounds__(256) void gemm_qkv(
    const __nv_bfloat16* __restrict__ Ah, const __nv_bfloat16* __restrict__ Al,
    const __nv_bfloat16* __restrict__ Wqh, const __nv_bfloat16* __restrict__ Wql,
    const __nv_bfloat16* __restrict__ Wkh, const __nv_bfloat16* __restrict__ Wkl,
    const __nv_bfloat16* __restrict__ Wvh, const __nv_bfloat16* __restrict__ Wvl,
    const float* __restrict__ bq, const float* __restrict__ bk,
    const float* __restrict__ bv,
    __nv_bfloat16* __restrict__ Qh, __nv_bfloat16* __restrict__ Ql,
    __nv_bfloat16* __restrict__ Kh, __nv_bfloat16* __restrict__ Kl,
    __nv_bfloat16* __restrict__ Vh, __nv_bfloat16* __restrict__ Vl) {
    extern __shared__ __align__(16) char smg[];
    const uint32_t sb = cvta_s(smg);
    const int tid = threadIdx.x, lane = tid & 31, wid = tid >> 5;
    const int wm = wid & 3, wn = wid >> 2;
    const int m0 = blockIdx.y * 128, n0 = blockIdx.x * 128;
    const int z = blockIdx.z;

    const __nv_bfloat16* Bh = (z == 0) ? Wqh : (z == 1) ? Wkh : Wvh;
    const __nv_bfloat16* Bl = (z == 0) ? Wql : (z == 1) ? Wkl : Wvl;
    const float* bias = (z == 0) ? bq : (z == 1) ? bk : bv;
    __nv_bfloat16* outH = (z == 0) ? Qh : (z == 1) ? Kh : Vh;
    __nv_bfloat16* outL = (z == 0) ? Ql : (z == 1) ? Kl : Vl;

    float acc[2][8][4];
#pragma unroll
    for (int i = 0; i < 2; i++)
#pragma unroll
        for (int j = 0; j < 8; j++)
#pragma unroll
            for (int k = 0; k < 4; k++) acc[i][j][k] = 0.0f;

    gemm_mainloop(sb, tid, lane, wm, wn, m0, n0, Ah, Al, Bh, Bl, acc);

    // Epilogue: bf16 hi/lo split into [B,H,T,D]
#pragma unroll
    for (int mf = 0; mf < 2; mf++) {
        int mg0 = m0 + wm * 32 + mf * 16 + (lane >> 2);
#pragma unroll
        for (int nf = 0; nf < 8; nf++) {
            int ng = n0 + wn * 64 + nf * 8 + (lane & 3) * 2;
            float b0v = bias[ng], b1v = bias[ng + 1];
#pragma unroll
            for (int half = 0; half < 2; half++) {
                int m = mg0 + half * 8;
                float v0 = acc[mf][nf][half * 2] + b0v;
                float v1 = acc[mf][nf][half * 2 + 1] + b1v;
                int bb = m >> 11, t = m & 2047, h = ng >> 6, d = ng & 63;
                size_t o = (((size_t)(bb * Hc + h)) * Tc + t) * Dc + d;
                uint32_t hiw, low;
                split_pack(v0, v1, hiw, low);
                *(uint32_t*)(outH + o) = hiw;
                *(uint32_t*)(outL + o) = low;
            }
        }
    }
}

// ---------------------------------------------------------------------------
// Output projection GEMM: fp32 out [M, C]
// ---------------------------------------------------------------------------
__global__ __launch_bounds__(256) void gemm_out(
    const __nv_bfloat16* __restrict__ Ah, const __nv_bfloat16* __restrict__ Al,
    const __nv_bfloat16* __restrict__ Bh, const __nv_bfloat16* __restrict__ Bl,
    const float* __restrict__ bias, float* __restrict__ out) {
    extern __shared__ __align__(16) char smg[];
    const uint32_t sb = cvta_s(smg);
    const int tid = threadIdx.x, lane = tid & 31, wid = tid >> 5;
    const int wm = wid & 3, wn = wid >> 2;
    const int m0 = blockIdx.y * 128, n0 = blockIdx.x * 128;

    float acc[2][8][4];
#pragma unroll
    for (int i = 0; i < 2; i++)
#pragma unroll
        for (int j = 0; j < 8; j++)
#pragma unroll
            for (int k = 0; k < 4; k++) acc[i][j][k] = 0.0f;

    gemm_mainloop(sb, tid, lane, wm, wn, m0, n0, Ah, Al, Bh, Bl, acc);

#pragma unroll
    for (int mf = 0; mf < 2; mf++) {
        int mg0 = m0 + wm * 32 + mf * 16 + (lane >> 2);
#pragma unroll
        for (int nf = 0; nf < 8; nf++) {
            int ng = n0 + wn * 64 + nf * 8 + (lane & 3) * 2;
            float b0v = bias[ng], b1v = bias[ng + 1];
#pragma unroll
            for (int half = 0; half < 2; half++) {
                int m = mg0 + half * 8;
                float2 v = make_float2(acc[mf][nf][half * 2] + b0v,
                                       acc[mf][nf][half * 2 + 1] + b1v);
                *(float2*)(out + (size_t)m * Cc + ng) = v;
            }
        }
    }
}

// ---------------------------------------------------------------------------
// Flash attention via mma.sync. Grid (T/64, B*H). 128 threads (4 warps,
// each warp owns 16 query rows). Q frags resident. KV tiles 64x64 hi/lo,
// double-buffered cp.async, single-barrier prefetch-then-compute loop.
// ---------------------------------------------------------------------------
#define ASR 144u
#define KH_OFF 0u
#define KL_OFF 9216u
#define VH_OFF 18432u
#define VL_OFF 27648u
#define KVBUF 36864u
#define ATTN_SMEM (2u * KVBUF)      // 73728 B

__device__ __forceinline__ void attn_load_kv(
    uint32_t base, int tid, size_t hb, int n0,
    const __nv_bfloat16* __restrict__ Kh, const __nv_bfloat16* __restrict__ Kl,
    const __nv_bfloat16* __restrict__ Vh, const __nv_bfloat16* __restrict__ Vl) {
#pragma unroll
    for (int it = 0; it < 4; it++) {
        int idx = tid + it * 128;          // 0..511
        int row = idx >> 3, seg = idx & 7; // row 0..63
        uint32_t so = (uint32_t)row * ASR + (uint32_t)seg * 16u;
        size_t g = hb + (size_t)(n0 + row) * Dc + seg * 8;
        CPA16(base + KH_OFF + so, Kh + g);
        CPA16(base + KL_OFF + so, Kl + g);
        CPA16(base + VH_OFF + so, Vh + g);
        CPA16(base + VL_OFF + so, Vl + g);
    }
}

__global__ __launch_bounds__(128) void attn_mma(
    const __nv_bfloat16* __restrict__ Qh, const __nv_bfloat16* __restrict__ Ql,
    const __nv_bfloat16* __restrict__ Kh, const __nv_bfloat16* __restrict__ Kl,
    const __nv_bfloat16* __restrict__ Vh, const __nv_bfloat16* __restrict__ Vl,
    __nv_bfloat16* __restrict__ Yh, __nv_bfloat16* __restrict__ Yl) {
    extern __shared__ __align__(16) char sma[];
    const uint32_t sb = cvta_s(sma);
    const int tid = threadIdx.x, lane = tid & 31, wid = tid >> 5;
    const int bh_i = blockIdx.y;
    const int m0 = blockIdx.x * 64;
    const size_t hb = (size_t)bh_i * Tc * Dc;
    const int NT = blockIdx.x + 1;

    // ---- Stage Q (64 rows) into buffer 0, pull frags, then release ----
#pragma unroll
    for (int it = 0; it < 4; it++) {
        int idx = tid + it * 128;
        int row = idx >> 3, seg = idx & 7;
        uint32_t so = (uint32_t)row * ASR + (uint32_t)seg * 16u;
        size_t g = hb + (size_t)(m0 + row) * Dc + seg * 8;
        CPA16(sb + KH_OFF + so, Qh + g);
        CPA16(sb + KL_OFF + so, Ql + g);
    }
    CPCOMMIT();
    CPWAIT(0);
    __syncthreads();

    uint32_t qfh[4][4], qfl[4][4];
    {
        const int arow = wid * 16 + (lane & 15);
        const int akof = (lane >> 4) << 3;
#pragma unroll
        for (int kf = 0; kf < 4; kf++) {
            uint32_t ao = (uint32_t)arow * ASR + (uint32_t)(kf * 16 + akof) * 2u;
            ldsm4(sb + KH_OFF + ao, qfh[kf][0], qfh[kf][1], qfh[kf][2], qfh[kf][3]);
            ldsm4(sb + KL_OFF + ao, qfl[kf][0], qfl[kf][1], qfl[kf][2], qfl[kf][3]);
        }
    }
    __syncthreads();

    attn_load_kv(sb, tid, hb, 0, Kh, Kl, Vh, Vl);
    CPCOMMIT();

    float oacc[8][4];
#pragma unroll
    for (int i = 0; i < 8; i++)
#pragma unroll
        for (int j = 0; j < 4; j++) oacc[i][j] = 0.0f;
    float rm[2] = {-1e30f, -1e30f};
    float rs[2] = {0.0f, 0.0f};

    const int brow = (lane & 7) + ((lane & 16) >> 1);
    const int bkof = lane & 8;
    const float sc = 0.125f;

    for (int nt = 0; nt < NT; nt++) {
        const int n0 = nt * 64;
        CPWAIT(0);
        __syncthreads();
        if (nt + 1 < NT) {
            attn_load_kv(sb + (uint32_t)((nt + 1) & 1) * KVBUF, tid, hb,
                         (nt + 1) * 64, Kh, Kl, Vh, Vl);
            CPCOMMIT();
        }
        const uint32_t base = sb + (uint32_t)(nt & 1) * KVBUF;

        // ---- S = Q K^T (3-term split) ----
        float s[8][4];
#pragma unroll
        for (int i = 0; i < 8; i++)
#pragma unroll
            for (int j = 0; j < 4; j++) s[i][j] = 0.0f;
#pragma unroll
        for (int kf = 0; kf < 4; kf++) {
            uint32_t kfh[4][4], kfl[4][4];
            const uint32_t bcb = (uint32_t)(kf * 16 + bkof) * 2u;
#pragma unroll
            for (int ng = 0; ng < 4; ng++) {
                uint32_t bo = (uint32_t)(ng * 16 + brow) * ASR + bcb;
                ldsm4(base + KH_OFF + bo, kfh[ng][0], kfh[ng][1], kfh[ng][2], kfh[ng][3]);
                ldsm4(base + KL_OFF + bo, kfl[ng][0], kfl[ng][1], kfl[ng][2], kfl[ng][3]);
            }
#pragma unroll
            for (int nf = 0; nf < 8; nf++) {
                uint32_t fh[2] = {kfh[nf >> 1][(nf & 1) * 2],
                                  kfh[nf >> 1][(nf & 1) * 2 + 1]};
                uint32_t fl[2] = {kfl[nf >> 1][(nf & 1) * 2],
                                  kfl[nf >> 1][(nf & 1) * 2 + 1]};
                mma16816(s[nf], qfh[kf], fh);
                mma16816(s[nf], qfh[kf], fl);
                mma16816(s[nf], qfl[kf], fh);
            }
        }

        // ---- scale + causal mask (only the diagonal tile masks) ----
        if (n0 == m0) {
            const int r0 = m0 + wid * 16 + (lane >> 2);
#pragma unroll
            for (int nf = 0; nf < 8; nf++) {
                const int c0 = n0 + nf * 8 + (lane & 3) * 2;
#pragma unroll
                for (int half = 0; half < 2; half++) {
                    const int row = r0 + half * 8;
                    s[nf][half * 2]     = (c0     <= row) ? s[nf][half * 2] * sc     : -1e30f;
                    s[nf][half * 2 + 1] = (c0 + 1 <= row) ? s[nf][half * 2 + 1] * sc : -1e30f;
                }
            }
        } else {
#pragma unroll
            for (int nf = 0; nf < 8; nf++)
#pragma unroll
                for (int j = 0; j < 4; j++) s[nf][j] *= sc;
        }

        // ---- online softmax (2 rows per thread) ----
        float tmax[2] = {-1e30f, -1e30f};
#pragma unroll
        for (int nf = 0; nf < 8; nf++) {
            tmax[0] = fmaxf(tmax[0], fmaxf(s[nf][0], s[nf][1]));
            tmax[1] = fmaxf(tmax[1], fmaxf(s[nf][2], s[nf][3]));
        }
#pragma unroll
        for (int h = 0; h < 2; h++) {
            tmax[h] = fmaxf(tmax[h], __shfl_xor_sync(0xffffffffu, tmax[h], 1));
            tmax[h] = fmaxf(tmax[h], __shfl_xor_sync(0xffffffffu, tmax[h], 2));
        }
        float nm0 = fmaxf(rm[0], tmax[0]);
        float nm1 = fmaxf(rm[1], tmax[1]);
        float corr0 = __expf(rm[0] - nm0);
        float corr1 = __expf(rm[1] - nm1);
        rm[0] = nm0; rm[1] = nm1;
        float ts0 = 0.0f, ts1 = 0.0f;
#pragma unroll
        for (int nf = 0; nf < 8; nf++) {
            s[nf][0] = __expf(s[nf][0] - nm0); ts0 += s[nf][0];
            s[nf][1] = __expf(s[nf][1] - nm0); ts0 += s[nf][1];
            s[nf][2] = __expf(s[nf][2] - nm1); ts1 += s[nf][2];
            s[nf][3] = __expf(s[nf][3] - nm1); ts1 += s[nf][3];
        }
        ts0 += __shfl_xor_sync(0xffffffffu, ts0, 1);
        ts0 += __shfl_xor_sync(0xffffffffu, ts0, 2);
        ts1 += __shfl_xor_sync(0xffffffffu, ts1, 1);
        ts1 += __shfl_xor_sync(0xffffffffu, ts1, 2);
        rs[0] = rs[0] * corr0 + ts0;
        rs[1] = rs[1] * corr1 + ts1;
#pragma unroll
        for (int df = 0; df < 8; df++) {
            oacc[df][0] *= corr0; oacc[df][1] *= corr0;
            oacc[df][2] *= corr1; oacc[df][3] *= corr1;
        }

        // ---- P frags (hi/lo) ----
        uint32_t pfh[4][4], pfl[4][4];
#pragma unroll
        for (int kf2 = 0; kf2 < 4; kf2++) {
            split_pack(s[2 * kf2][0], s[2 * kf2][1], pfh[kf2][0], pfl[kf2][0]);
            split_pack(s[2 * kf2][2], s[2 * kf2][3], pfh[kf2][1], pfl[kf2][1]);
            split_pack(s[2 * kf2 + 1][0], s[2 * kf2 + 1][1], pfh[kf2][2], pfl[kf2][2]);
            split_pack(s[2 * kf2 + 1][2], s[2 * kf2 + 1][3], pfh[kf2][3], pfl[kf2][3]);
        }

        // ---- O += P V (3-term) ----
#pragma unroll
        for (int df = 0; df < 8; df++) {
#pragma unroll
            for (int kf2 = 0; kf2 < 4; kf2++) {
                uint32_t vo = (uint32_t)(kf2 * 16 + (lane & 15)) * ASR +
                              (uint32_t)df * 16u;
                uint32_t vb[2], vlb[2];
                ldsm2t(base + VH_OFF + vo, vb[0], vb[1]);
                ldsm2t(base + VL_OFF + vo, vlb[0], vlb[1]);
                mma16816(oacc[df], pfh[kf2], vb);
                mma16816(oacc[df], pfh[kf2], vlb);
                mma16816(oacc[df], pfl[kf2], vb);
            }
        }
    }

    // ---- epilogue: normalize, split to bf16 hi/lo, write y [B,T,C] ----
    const float inv0 = 1.0f / rs[0];
    const float inv1 = 1.0f / rs[1];
    const int b = bh_i >> 4, h = bh_i & 15;
    const int t0 = m0 + wid * 16 + (lane >> 2);
#pragma unroll
    for (int df = 0; df < 8; df++) {
        const int d = df * 8 + (lane & 3) * 2;
#pragma unroll
        for (int half = 0; half < 2; half++) {
            const int t = t0 + half * 8;
            const float inv = half ? inv1 : inv0;
            float v0 = oacc[df][half * 2] * inv;
            float v1 = oacc[df][half * 2 + 1] * inv;
            uint32_t hiw, low;
            split_pack(v0, v1, hiw, low);
            size_t o = ((size_t)(b * Tc + t)) * Cc + h * Dc + d;
            *(uint32_t*)(Yh + o) = hiw;
            *(uint32_t*)(Yl + o) = low;
        }
    }
}

// ---------------------------------------------------------------------------
extern "C" void kernel_launch(void* const* d_in, const int* in_sizes, int n_in,
                              void* d_out, int out_size) {
    const float* x  = (const float*)d_in[0];
    const float* Wk = (const float*)d_in[1];
    const float* bk = (const float*)d_in[2];
    const float* Wq = (const float*)d_in[3];
    const float* bq = (const float*)d_in[4];
    const float* Wv = (const float*)d_in[5];
    const float* bv = (const float*)d_in[6];
    const float* Wp = (const float*)d_in[7];
    const float* bp = (const float*)d_in[8];
    float* out = (float*)d_out;

    __nv_bfloat16 *xh, *xl, *yh, *yl;
    __nv_bfloat16 *qh, *ql, *kh, *kl, *vh, *vl;
    __nv_bfloat16 *wqh, *wql, *wkh, *wkl, *wvh, *wvl, *wph, *wpl;
    cudaGetSymbolAddress((void**)&xh, g_xh);
    cudaGetSymbolAddress((void**)&xl, g_xl);
    cudaGetSymbolAddress((void**)&yh, g_yh);
    cudaGetSymbolAddress((void**)&yl, g_yl);
    cudaGetSymbolAddress((void**)&qh, g_qh);
    cudaGetSymbolAddress((void**)&ql, g_ql);
    cudaGetSymbolAddress((void**)&kh, g_kh);
    cudaGetSymbolAddress((void**)&kl, g_kl);
    cudaGetSymbolAddress((void**)&vh, g_vh);
    cudaGetSymbolAddress((void**)&vl, g_vl);
    cudaGetSymbolAddress((void**)&wqh, g_wqh);
    cudaGetSymbolAddress((void**)&wql, g_wql);
    cudaGetSymbolAddress((void**)&wkh, g_wkh);
    cudaGetSymbolAddress((void**)&wkl, g_wkl);
    cudaGetSymbolAddress((void**)&wvh, g_wvh);
    cudaGetSymbolAddress((void**)&wvl, g_wvl);
    cudaGetSymbolAddress((void**)&wph, g_wph);
    cudaGetSymbolAddress((void**)&wpl, g_wpl);

    cudaFuncSetAttribute(gemm_qkv, cudaFuncAttributeMaxDynamicSharedMemorySize,
                         (int)GEMM_SMEM);
    cudaFuncSetAttribute(gemm_out, cudaFuncAttributeMaxDynamicSharedMemorySize,
                         (int)GEMM_SMEM);
    cudaFuncSetAttribute(attn_mma, cudaFuncAttributeMaxDynamicSharedMemorySize,
                         (int)ATTN_SMEM);

    split_bf16<<<Mtot * Cc / 4 / 256, 256>>>(x, xh, xl);
    split_bf16<<<Cc * Cc / 4 / 256, 256>>>(Wq, wqh, wql);
    split_bf16<<<Cc * Cc / 4 / 256, 256>>>(Wk, wkh, wkl);
    split_bf16<<<Cc * Cc / 4 / 256, 256>>>(Wv, wvh, wvl);
    split_bf16<<<Cc * Cc / 4 / 256, 256>>>(Wp, wph, wpl);

    dim3 gqkv(Cc / 128, Mtot / 128, 3);   // (8, 32, 3) = 768 CTAs, one launch
    gemm_qkv<<<gqkv, 256, GEMM_SMEM>>>(xh, xl, wqh, wql, wkh, wkl, wvh, wvl,
                                       bq, bk, bv, qh, ql, kh, kl, vh, vl);

    dim3 agrid(Tc / 64, BHc);             // (32, 32)
    attn_mma<<<agrid, 128, ATTN_SMEM>>>(qh, ql, kh, kl, vh, vl, yh, yl);

    dim3 ggrid(Cc / 128, Mtot / 128);     // (8, 32)
    gemm_out<<<ggrid, 256, GEMM_SMEM>>>(yh, yl, wph, wpl, bp, out);
}